// round 1
// baseline (speedup 1.0000x reference)
#include <cuda_runtime.h>

#define L_EXP 16
#define IN0   7
#define C0    16
#define C1    32
#define C2    16
#define NEG   0.2f

// Transposed smem sizes (floats), expert index innermost for conflict-free LDS
#define W0T_SZ (IN0 * C0 * L_EXP)   // 1792
#define B0T_SZ (C0 * L_EXP)         // 256
#define W1T_SZ (C0 * C1 * L_EXP)    // 8192
#define B1T_SZ (C1 * L_EXP)         // 512
#define W2T_SZ (C1 * C2 * L_EXP)    // 8192
#define B2T_SZ (C2 * L_EXP)         // 256
#define SM_FLOATS (W0T_SZ + B0T_SZ + W1T_SZ + B1T_SZ + W2T_SZ + B2T_SZ) // 19200
#define SM_BYTES  (SM_FLOATS * 4)   // 76800

#define TPB 256
#define PPT 2                       // points per thread
#define PPB (TPB * PPT)             // 512 points per block

__global__ __launch_bounds__(TPB)
void wnet_kernel(const float* __restrict__ x,
                 const int*   __restrict__ idx,
                 const float* __restrict__ W0, const float* __restrict__ b0,
                 const float* __restrict__ W1, const float* __restrict__ b1,
                 const float* __restrict__ W2, const float* __restrict__ b2,
                 float* __restrict__ out, int n)
{
    extern __shared__ float sm[];
    float* sW0 = sm;
    float* sB0 = sW0 + W0T_SZ;
    float* sW1 = sB0 + B0T_SZ;
    float* sB1 = sW1 + W1T_SZ;
    float* sW2 = sB1 + B1T_SZ;
    float* sB2 = sW2 + W2T_SZ;

    const int t = threadIdx.x;

    // ---- Stage weights into smem, transposed to expert-innermost ----
    // dest sW0[(i*C0+o)*16 + e]  <- W0[e][i][o] = W0[(e*IN0+i)*C0 + o]
    for (int d = t; d < W0T_SZ; d += TPB) {
        int e = d & 15, io = d >> 4;
        int o = io & 15, i = io >> 4;
        sW0[d] = W0[(e * IN0 + i) * C0 + o];
    }
    for (int d = t; d < B0T_SZ; d += TPB) {
        int e = d & 15, o = d >> 4;
        sB0[d] = b0[e * C0 + o];
    }
    // dest sW1[(i*C1+o)*16 + e]  <- W1[(e*C0+i)*C1 + o]
    for (int d = t; d < W1T_SZ; d += TPB) {
        int e = d & 15, io = d >> 4;
        int o = io & 31, i = io >> 5;
        sW1[d] = W1[(e * C0 + i) * C1 + o];
    }
    for (int d = t; d < B1T_SZ; d += TPB) {
        int e = d & 15, o = d >> 4;
        sB1[d] = b1[e * C1 + o];
    }
    // dest sW2[(i*C2+o)*16 + e]  <- W2[(e*C1+i)*C2 + o]
    for (int d = t; d < W2T_SZ; d += TPB) {
        int e = d & 15, io = d >> 4;
        int o = io & 15, i = io >> 4;
        sW2[d] = W2[(e * C1 + i) * C2 + o];
    }
    for (int d = t; d < B2T_SZ; d += TPB) {
        int e = d & 15, o = d >> 4;
        sB2[d] = b2[e * C2 + o];
    }
    __syncthreads();

    const int base = blockIdx.x * PPB + t;

    #pragma unroll
    for (int rep = 0; rep < PPT; rep++) {
        const int p = base + rep * TPB;
        if (p < n) {
            const int e = idx[p];
            const float* xp = x + (size_t)p * IN0;

            float h0[IN0];
            #pragma unroll
            for (int i = 0; i < IN0; i++) h0[i] = xp[i];

            // Layer 0: 7 -> 16
            float h1[C0];
            #pragma unroll
            for (int o = 0; o < C0; o++) {
                float acc = sB0[o * L_EXP + e];
                #pragma unroll
                for (int i = 0; i < IN0; i++)
                    acc = fmaf(h0[i], sW0[(i * C0 + o) * L_EXP + e], acc);
                h1[o] = fmaxf(acc, NEG * acc);
            }

            // Layer 1: 16 -> 32
            float h2[C1];
            #pragma unroll
            for (int o = 0; o < C1; o++) {
                float acc = sB1[o * L_EXP + e];
                #pragma unroll
                for (int i = 0; i < C0; i++)
                    acc = fmaf(h1[i], sW1[(i * C1 + o) * L_EXP + e], acc);
                h2[o] = fmaxf(acc, NEG * acc);
            }

            // Layer 2: 32 -> 16
            float ho[C2];
            #pragma unroll
            for (int o = 0; o < C2; o++) {
                float acc = sB2[o * L_EXP + e];
                #pragma unroll
                for (int i = 0; i < C1; i++)
                    acc = fmaf(h2[i], sW2[(i * C2 + o) * L_EXP + e], acc);
                ho[o] = fmaxf(acc, NEG * acc);
            }

            // Vectorized output store: 16 floats = 4x float4, 64B-aligned
            float4* op = reinterpret_cast<float4*>(out + (size_t)p * C2);
            op[0] = make_float4(ho[0],  ho[1],  ho[2],  ho[3]);
            op[1] = make_float4(ho[4],  ho[5],  ho[6],  ho[7]);
            op[2] = make_float4(ho[8],  ho[9],  ho[10], ho[11]);
            op[3] = make_float4(ho[12], ho[13], ho[14], ho[15]);
        }
    }
}

extern "C" void kernel_launch(void* const* d_in, const int* in_sizes, int n_in,
                              void* d_out, int out_size)
{
    const float* x   = (const float*)d_in[0];
    const int*   idx = (const int*)  d_in[1];
    const float* W0  = (const float*)d_in[2];
    const float* b0  = (const float*)d_in[3];
    const float* W1  = (const float*)d_in[4];
    const float* b1  = (const float*)d_in[5];
    const float* W2  = (const float*)d_in[6];
    const float* b2  = (const float*)d_in[7];
    float* out = (float*)d_out;

    const int n = in_sizes[1];  // idx has one entry per point

    cudaFuncSetAttribute(wnet_kernel,
                         cudaFuncAttributeMaxDynamicSharedMemorySize, SM_BYTES);

    const int grid = (n + PPB - 1) / PPB;
    wnet_kernel<<<grid, TPB, SM_BYTES>>>(x, idx, W0, b0, W1, b1, W2, b2, out, n);
}